// round 4
// baseline (speedup 1.0000x reference)
#include <cuda_runtime.h>

#define N_NODESC 100000
#define N_EDGESC 1600000
#define NUM_GRAPHSC 1024
#define IN_FEATC 7
#define HC 128
#define H3C 384
#define BN_EPSF 1e-5f

// ---------------- scratch (static device globals; no runtime alloc) ----------------
__device__ float g_z0[(size_t)N_NODESC * IN_FEATC];
__device__ float g_t[(size_t)N_NODESC * HC];
__device__ float g_z[(size_t)N_NODESC * HC];
__device__ float g_hcat[(size_t)N_NODESC * H3C];
__device__ float g_pool[(size_t)NUM_GRAPHSC * H3C];
__device__ float g_z1[(size_t)NUM_GRAPHSC * 256];
__device__ int   g_deg[N_NODESC];
__device__ int   g_ptr[N_NODESC + 1];
__device__ int   g_cur[N_NODESC];
__device__ int   g_col[N_EDGESC];
__device__ int   g_gstart[NUM_GRAPHSC + 1];

// ---------------- f32x2 helpers (Blackwell packed fp32) ----------------
__device__ __forceinline__ unsigned long long pack2(float x) {
    unsigned long long r;
    asm("mov.b64 %0, {%1, %2};" : "=l"(r) : "f"(x), "f"(x));
    return r;
}
__device__ __forceinline__ unsigned long long fma2(unsigned long long a, unsigned long long b,
                                                   unsigned long long c) {
    unsigned long long d;
    asm("fma.rn.f32x2 %0, %1, %2, %3;" : "=l"(d) : "l"(a), "l"(b), "l"(c));
    return d;
}
__device__ __forceinline__ float2 unpack2(unsigned long long v) {
    float2 f;
    asm("mov.b64 {%0, %1}, %2;" : "=f"(f.x), "=f"(f.y) : "l"(v));
    return f;
}

// ---------------- CSR build ----------------
__global__ void k_zero_deg() {
    int i = blockIdx.x * blockDim.x + threadIdx.x;
    if (i < N_NODESC) g_deg[i] = 0;
}

__global__ void k_hist(const int* __restrict__ ei) {
    int stride = gridDim.x * blockDim.x;
    for (int e = blockIdx.x * blockDim.x + threadIdx.x; e < N_EDGESC; e += stride) {
        atomicAdd(&g_deg[ei[N_EDGESC + e]], 1);
    }
}

// single-block chunked exclusive scan over degrees -> g_ptr, g_cur
__global__ void k_scan() {
    __shared__ int s[1024];
    const int t = threadIdx.x;
    const int CHUNK = 98; // 1024*98 = 100352 >= 100000
    int base = t * CHUNK;
    int loc = 0;
    for (int i = 0; i < CHUNK; ++i) {
        int idx = base + i;
        if (idx < N_NODESC) loc += g_deg[idx];
    }
    s[t] = loc;
    __syncthreads();
    for (int off = 1; off < 1024; off <<= 1) {
        int v = (t >= off) ? s[t - off] : 0;
        __syncthreads();
        s[t] += v;
        __syncthreads();
    }
    int run = s[t] - loc; // exclusive prefix for this thread's chunk
    for (int i = 0; i < CHUNK; ++i) {
        int idx = base + i;
        if (idx < N_NODESC) {
            g_ptr[idx] = run;
            g_cur[idx] = run;
            run += g_deg[idx];
        }
    }
    if (t == 1023) g_ptr[N_NODESC] = s[1023];
}

__global__ void k_scatter(const int* __restrict__ ei) {
    int stride = gridDim.x * blockDim.x;
    for (int e = blockIdx.x * blockDim.x + threadIdx.x; e < N_EDGESC; e += stride) {
        int d = ei[N_EDGESC + e];
        int p = atomicAdd(&g_cur[d], 1);
        g_col[p] = ei[e];
    }
}

// graph boundaries via binary search on sorted batch
__global__ void k_gstart(const int* __restrict__ batch) {
    int g = blockIdx.x * blockDim.x + threadIdx.x;
    if (g > NUM_GRAPHSC) return;
    int lo = 0, hi = N_NODESC;
    while (lo < hi) {
        int mid = (lo + hi) >> 1;
        if (batch[mid] < g) lo = mid + 1; else hi = mid;
    }
    g_gstart[g] = lo;
}

// ---------------- layer 0 aggregation (7 feats): z0 = x + sum_{src->n} x[src] ----------------
__global__ void k_agg0(const float* __restrict__ x) {
    int gidx = blockIdx.x * blockDim.x + threadIdx.x;
    int node = gidx >> 5;
    int lane = gidx & 31;
    if (node >= N_NODESC) return;
    float acc[IN_FEATC];
#pragma unroll
    for (int f = 0; f < IN_FEATC; ++f) acc[f] = 0.f;
    int s = g_ptr[node], e = g_ptr[node + 1];
    for (int p = s + lane; p < e; p += 32) {
        int src = g_col[p];
        const float* xp = x + (size_t)src * IN_FEATC;
#pragma unroll
        for (int f = 0; f < IN_FEATC; ++f) acc[f] += xp[f];
    }
#pragma unroll
    for (int f = 0; f < IN_FEATC; ++f) {
#pragma unroll
        for (int off = 16; off > 0; off >>= 1)
            acc[f] += __shfl_down_sync(0xffffffffu, acc[f], off);
    }
    if (lane == 0) {
        const float* xp = x + (size_t)node * IN_FEATC;
        float* zp = g_z0 + (size_t)node * IN_FEATC;
#pragma unroll
        for (int f = 0; f < IN_FEATC; ++f) zp[f] = xp[f] + acc[f];
    }
}

// ---------------- t = relu(z0 @ w1_0 + b1_0), K = 7 ----------------
__global__ void k_fc7(const float* __restrict__ w, const float* __restrict__ b) {
    __shared__ float ws[IN_FEATC * HC];
    __shared__ float bs[HC];
    if (threadIdx.x < HC) bs[threadIdx.x] = b[threadIdx.x];
    for (int i = threadIdx.x; i < IN_FEATC * HC; i += blockDim.x) ws[i] = w[i];
    __syncthreads();
    int gid = blockIdx.x * blockDim.x + threadIdx.x;
    int n = gid >> 7;
    int j = gid & 127;
    const float* zp = g_z0 + (size_t)n * IN_FEATC;
    float acc = bs[j];
#pragma unroll
    for (int k = 0; k < IN_FEATC; ++k) acc = fmaf(zp[k], ws[k * HC + j], acc);
    g_t[(size_t)n * HC + j] = fmaxf(acc, 0.f);
}

// ---------------- main aggregation: z[n] = h[n] + sum h[src], 128 feats ----------------
__global__ void k_agg(const float* __restrict__ h, int ldh) {
    int gidx = blockIdx.x * blockDim.x + threadIdx.x;
    int node = gidx >> 5;
    int lane = gidx & 31;
    if (node >= N_NODESC) return;
    int fo = lane << 2;
    float4 acc = *(const float4*)(h + (size_t)node * ldh + fo);
    int s = g_ptr[node], e = g_ptr[node + 1];
    for (int p = s; p < e; ++p) {
        int src = g_col[p];
        float4 v = *(const float4*)(h + (size_t)src * ldh + fo);
        acc.x += v.x; acc.y += v.y; acc.z += v.z; acc.w += v.w;
    }
    *(float4*)(g_z + (size_t)node * HC + fo) = acc;
}

// ---------------- 128x128xK=128 GEMM, fused bias + relu, f32x2 FFMA2 path ----------------
// C[M x 128] = relu(A[M x 128] @ B[128 x 128] + bias)
__global__ void __launch_bounds__(256, 1)
k_gemm128(const float* __restrict__ A, int lda, const float* __restrict__ B,
          const float* __restrict__ bias, float* __restrict__ C, int ldc, int M) {
    extern __shared__ float sm[];
    float* As = sm;                  // [128][129], k-major: As[k*129 + r]
    float* Bs = sm + 128 * 129;      // [128][132]: Bs[k*132 + c]
    const int tid = threadIdx.x;
    const int row0 = blockIdx.x * 128;

    // stage A (transposed) — 4096 float4 slots
#pragma unroll
    for (int it = 0; it < 16; ++it) {
        int lin = tid + it * 256;
        int r = lin >> 5;
        int k4 = (lin & 31) << 2;
        float4 v = make_float4(0.f, 0.f, 0.f, 0.f);
        int row = row0 + r;
        if (row < M) v = *(const float4*)(A + (size_t)row * lda + k4);
        As[(k4 + 0) * 129 + r] = v.x;
        As[(k4 + 1) * 129 + r] = v.y;
        As[(k4 + 2) * 129 + r] = v.z;
        As[(k4 + 3) * 129 + r] = v.w;
    }
    // stage B
#pragma unroll
    for (int it = 0; it < 16; ++it) {
        int lin = tid + it * 256;
        int k = lin >> 5;
        int c4 = (lin & 31) << 2;
        *(float4*)(Bs + k * 132 + c4) = *(const float4*)(B + k * 128 + c4);
    }
    __syncthreads();

    const int lane = tid & 31;
    const int warp = tid >> 5;
    const int tx = lane & 15;
    const int tyw = lane >> 4;
    const int r0 = (warp * 2 + tyw) * 8;   // 8 consecutive rows per thread
    // cols: tx*2 + jj*32 (+1)

    unsigned long long acc[8][4];
#pragma unroll
    for (int i = 0; i < 8; ++i)
#pragma unroll
        for (int jj = 0; jj < 4; ++jj) acc[i][jj] = 0ull;

#pragma unroll 2
    for (int k = 0; k < 128; ++k) {
        const float* ak = As + k * 129 + r0;
        const float* bk = Bs + k * 132 + tx * 2;
        unsigned long long b2[4];
#pragma unroll
        for (int jj = 0; jj < 4; ++jj)
            b2[jj] = *(const unsigned long long*)(bk + jj * 32);
#pragma unroll
        for (int i = 0; i < 8; ++i) {
            unsigned long long a2 = pack2(ak[i]);
#pragma unroll
            for (int jj = 0; jj < 4; ++jj) acc[i][jj] = fma2(a2, b2[jj], acc[i][jj]);
        }
    }

#pragma unroll
    for (int jj = 0; jj < 4; ++jj) {
        int c = tx * 2 + jj * 32;
        float2 bb = *(const float2*)(bias + c);
#pragma unroll
        for (int i = 0; i < 8; ++i) {
            int row = row0 + r0 + i;
            if (row < M) {
                float2 v = unpack2(acc[i][jj]);
                v.x = fmaxf(v.x + bb.x, 0.f);
                v.y = fmaxf(v.y + bb.y, 0.f);
                *(float2*)(C + (size_t)row * ldc + c) = v;
            }
        }
    }
}

// ---------------- global add pool: g[gid] = sum_{n in graph} hcat[n] ----------------
__global__ void k_pool() {
    int g = blockIdx.x;
    int f = threadIdx.x;            // 384 threads
    int s = g_gstart[g], e = g_gstart[g + 1];
    float acc = 0.f;
    for (int n = s; n < e; ++n) acc += g_hcat[(size_t)n * H3C + f];
    g_pool[(size_t)g * H3C + f] = acc;
}

// ---------------- classifier stage 1: z1 = relu(bn(g @ clf_w1 + clf_b1)) ----------------
__global__ void k_clf1(const float* __restrict__ w, const float* __restrict__ b,
                       const float* __restrict__ gamma, const float* __restrict__ beta,
                       const float* __restrict__ mean, const float* __restrict__ var) {
    __shared__ float gs[16 * H3C]; // 24 KB
    const int r0 = blockIdx.x * 16;
    for (int i = threadIdx.x; i < 16 * H3C; i += blockDim.x)
        gs[i] = g_pool[(size_t)r0 * H3C + i];
    __syncthreads();
    const int c = threadIdx.x; // 256 cols
    float acc[16];
#pragma unroll
    for (int i = 0; i < 16; ++i) acc[i] = 0.f;
    for (int k = 0; k < H3C; ++k) {
        float wv = w[k * 256 + c];
#pragma unroll
        for (int i = 0; i < 16; ++i) acc[i] = fmaf(gs[i * H3C + k], wv, acc[i]);
    }
    float bb = b[c];
    float sc = rsqrtf(var[c] + BN_EPSF) * gamma[c];
    float mn = mean[c];
    float bt = beta[c];
#pragma unroll
    for (int i = 0; i < 16; ++i) {
        float v = (acc[i] + bb - mn) * sc + bt;
        g_z1[(size_t)(r0 + i) * 256 + c] = fmaxf(v, 0.f);
    }
}

// ---------------- classifier stage 2: out = z1 @ clf_w2 + clf_b2 ----------------
__global__ void k_clf2(const float* __restrict__ w2, const float* __restrict__ b2,
                       float* __restrict__ out) {
    __shared__ float w2s[512];
    __shared__ float b2s[2];
    // FIX: strided cooperative load (block has 256 threads; old guarded load
    // left w2s[256..511] as stale shared memory -> garbage classifier output)
    for (int i = threadIdx.x; i < 512; i += blockDim.x) w2s[i] = w2[i];
    if (threadIdx.x < 2) b2s[threadIdx.x] = b2[threadIdx.x];
    __syncthreads();
    int warp = threadIdx.x >> 5;
    int lane = threadIdx.x & 31;
    int r = blockIdx.x * 8 + warp;
    float a0 = 0.f, a1 = 0.f;
    for (int k = lane; k < 256; k += 32) {
        float v = g_z1[(size_t)r * 256 + k];
        a0 = fmaf(v, w2s[2 * k], a0);
        a1 = fmaf(v, w2s[2 * k + 1], a1);
    }
#pragma unroll
    for (int off = 16; off > 0; off >>= 1) {
        a0 += __shfl_down_sync(0xffffffffu, a0, off);
        a1 += __shfl_down_sync(0xffffffffu, a1, off);
    }
    if (lane == 0) {
        out[2 * r] = a0 + b2s[0];
        out[2 * r + 1] = a1 + b2s[1];
    }
}

// ---------------- launch ----------------
extern "C" void kernel_launch(void* const* d_in, const int* in_sizes, int n_in,
                              void* d_out, int out_size) {
    const float* x      = (const float*)d_in[0];
    const int*   ei     = (const int*)d_in[1];
    const int*   batch  = (const int*)d_in[2];
    const float* w1[3]  = {(const float*)d_in[3], (const float*)d_in[7],  (const float*)d_in[11]};
    const float* b1[3]  = {(const float*)d_in[4], (const float*)d_in[8],  (const float*)d_in[12]};
    const float* w2[3]  = {(const float*)d_in[5], (const float*)d_in[9],  (const float*)d_in[13]};
    const float* b2[3]  = {(const float*)d_in[6], (const float*)d_in[10], (const float*)d_in[14]};
    const float* clf_w1 = (const float*)d_in[15];
    const float* clf_b1 = (const float*)d_in[16];
    const float* clf_w2 = (const float*)d_in[17];
    const float* clf_b2 = (const float*)d_in[18];
    const float* bn_g   = (const float*)d_in[19];
    const float* bn_b   = (const float*)d_in[20];
    const float* bn_m   = (const float*)d_in[21];
    const float* bn_v   = (const float*)d_in[22];
    float* out = (float*)d_out;

    float *p_t, *p_z, *p_hcat;
    cudaGetSymbolAddress((void**)&p_t, g_t);
    cudaGetSymbolAddress((void**)&p_z, g_z);
    cudaGetSymbolAddress((void**)&p_hcat, g_hcat);

    const int gemm_smem = (128 * 129 + 128 * 132) * 4;
    cudaFuncSetAttribute(k_gemm128, cudaFuncAttributeMaxDynamicSharedMemorySize, gemm_smem);

    // CSR build
    k_zero_deg<<<(N_NODESC + 255) / 256, 256>>>();
    k_hist<<<1024, 256>>>(ei);
    k_scan<<<1, 1024>>>();
    k_scatter<<<1024, 256>>>(ei);
    k_gstart<<<(NUM_GRAPHSC + 1 + 255) / 256, 256>>>(batch);

    const int aggBlocks = N_NODESC / 8; // warp per node, 8 warps per block
    const int gemmBlocks = (N_NODESC + 127) / 128;

    // layer 0
    k_agg0<<<aggBlocks, 256>>>(x);
    k_fc7<<<(N_NODESC * HC) / 256, 256>>>(w1[0], b1[0]);
    k_gemm128<<<gemmBlocks, 256, gemm_smem>>>(p_t, HC, w2[0], b2[0], p_hcat + 0, H3C, N_NODESC);

    // layers 1,2
    for (int l = 1; l < 3; ++l) {
        k_agg<<<aggBlocks, 256>>>(p_hcat + (l - 1) * HC, H3C);
        k_gemm128<<<gemmBlocks, 256, gemm_smem>>>(p_z, HC, w1[l], b1[l], p_t, HC, N_NODESC);
        k_gemm128<<<gemmBlocks, 256, gemm_smem>>>(p_t, HC, w2[l], b2[l], p_hcat + l * HC, H3C, N_NODESC);
    }

    // pool + classifier
    k_pool<<<NUM_GRAPHSC, H3C>>>();
    k_clf1<<<NUM_GRAPHSC / 16, 256>>>(clf_w1, clf_b1, bn_g, bn_b, bn_m, bn_v);
    k_clf2<<<NUM_GRAPHSC / 8, 256>>>(clf_w2, clf_b2, out);
}